// round 6
// baseline (speedup 1.0000x reference)
#include <cuda_runtime.h>
#include <cuda_fp16.h>
#include <cstdint>

// Problem dims
#define S_DIM   32
#define B_DIM   256
#define IN_DIM  1024
#define OUT_DIM 1024

// ---------------------------------------------------------------------------
// Scratch (device globals)
// ---------------------------------------------------------------------------
__device__ __align__(128) __half g_xf16[(size_t)S_DIM * B_DIM * IN_DIM];   // 17 MB
__device__ __align__(128) float  g_sigma[(size_t)OUT_DIM * IN_DIM];        // 4 MB

__device__ __forceinline__ float softplusf(float x) {
    return (x > 15.0f) ? x : log1pf(expf(x));
}

__device__ __forceinline__ uint32_t smem_to_u32(const void* smem_ptr) {
    uint32_t addr;
    asm("{ .reg .u64 tmp; cvta.to.shared.u64 tmp, %1; cvt.u32.u64 %0, tmp; }"
        : "=r"(addr) : "l"(smem_ptr));
    return addr;
}

__device__ __forceinline__ void cp_async16(uint32_t smem_dst, const void* gptr) {
    asm volatile("cp.async.cg.shared.global [%0], [%1], 16;"
                 :: "r"(smem_dst), "l"(gptr) : "memory");
}

__device__ __forceinline__ void ldmatrix_x4(uint32_t r[4], uint32_t addr) {
    asm volatile("ldmatrix.sync.aligned.m8n8.x4.shared.b16 {%0,%1,%2,%3}, [%4];"
                 : "=r"(r[0]), "=r"(r[1]), "=r"(r[2]), "=r"(r[3]) : "r"(addr));
}

__device__ __forceinline__ void mma16816(float c[4],
                                         const uint32_t a[4],
                                         uint32_t b0, uint32_t b1) {
    asm volatile(
        "mma.sync.aligned.m16n8k16.row.col.f32.f16.f16.f32 "
        "{%0,%1,%2,%3}, {%4,%5,%6,%7}, {%8,%9}, {%0,%1,%2,%3};"
        : "+f"(c[0]), "+f"(c[1]), "+f"(c[2]), "+f"(c[3])
        : "r"(a[0]), "r"(a[1]), "r"(a[2]), "r"(a[3]), "r"(b0), "r"(b1));
}

// SW128 swizzle: byte address of 16B-quad (row, colq) in a 128-row x 128B tile.
__device__ __forceinline__ uint32_t sw128(int row, int colq) {
    return ((uint32_t)row << 7) + ((uint32_t)((colq ^ (row & 7)) & 7) << 4);
}

// ---------------------------------------------------------------------------
// Kernel 1: g_sigma = softplus(weight_rho)   (fp32, 4 MB, L2-resident after)
// ---------------------------------------------------------------------------
__global__ __launch_bounds__(256)
void prep_sigma_kernel(const float* __restrict__ wrho)
{
    const int q = blockIdx.x * 256 + threadIdx.x;    // 0..262143
    const float4 r = *reinterpret_cast<const float4*>(wrho + q * 4);
    float4 sg;
    sg.x = softplusf(r.x);
    sg.y = softplusf(r.y);
    sg.z = softplusf(r.z);
    sg.w = softplusf(r.w);
    *reinterpret_cast<float4*>(g_sigma + q * 4) = sg;
}

// ---------------------------------------------------------------------------
// Kernel 2: x_f16 = (half) input
// ---------------------------------------------------------------------------
__global__ __launch_bounds__(256)
void prep_x_kernel(const float* __restrict__ input)
{
    const int e4 = blockIdx.x * 256 + threadIdx.x;   // 0 .. 2097151
    const size_t e = (size_t)e4 * 4;
    const float4 x = *reinterpret_cast<const float4*>(input + e);
    __half2 h0 = __floats2half2_rn(x.x, x.y);
    __half2 h1 = __floats2half2_rn(x.z, x.w);
    uint2 o;
    o.x = *reinterpret_cast<unsigned*>(&h0);
    o.y = *reinterpret_cast<unsigned*>(&h1);
    reinterpret_cast<uint2*>(g_xf16)[e4] = o;
}

// ---------------------------------------------------------------------------
// Kernel 3: FUSED variational GEMM.
// B tile (weights) is generated in-SMEM each K-chunk:
//   w = fmaf(sigma[o,i], eps_w[s,o,i], mu[o,i])  -> half -> swizzled STS
// eps_w fp32 is register-prefetched one chunk ahead (DRAM latency overlaps
// the current chunk's MMA).  A tile streams via cp.async from g_xf16.
// CTA tile M=128 x N=128, K=1024 in 16 chunks of 64. 8 warps (2x4).
// Grid: (ntile=8, mtile=2, s=32) = 512 CTAs, 256 threads.
// ---------------------------------------------------------------------------
#define KC 64
#define NCHUNK (IN_DIM / KC)          // 16
#define TILE_BYTES (128 * 128)        // 16 KB = 1024 16B-quads per tile
#define STAGE_BYTES (2 * TILE_BYTES)  // A + B per stage
#define GEMM_DYN_SMEM (1024 + 2 * STAGE_BYTES)

__global__ __launch_bounds__(256, 1)
void gemm_fused_kernel(const float* __restrict__ wmu,
                       const float* __restrict__ epsw,
                       const float* __restrict__ bias_mu,
                       const float* __restrict__ bias_rho,
                       const float* __restrict__ eps_b,
                       float* __restrict__ out)
{
    extern __shared__ char dynsmem[];
    __shared__ float s_bias[128];

    const int tid = threadIdx.x;
    const int wid = tid >> 5;
    const int lid = tid & 31;
    const int ntile = blockIdx.x;   // 0..7
    const int mtile = blockIdx.y;   // 0..1
    const int s     = blockIdx.z;   // 0..31

    uint32_t base = smem_to_u32(dynsmem);
    base = (base + 1023u) & ~1023u;
    const uint32_t smA0 = base;
    const uint32_t smB0 = base + TILE_BYTES;

    // Fused bias
    if (tid < 128) {
        const int o = ntile * 128 + tid;
        s_bias[tid] = fmaf(softplusf(bias_rho[o]), eps_b[s * OUT_DIM + o], bias_mu[o]);
    }

    const __half* Ag = g_xf16 + (size_t)(s * B_DIM + mtile * 128) * IN_DIM;

    // B-production addressing: thread owns row r = tid>>1 of the B tile
    // (o = ntile*128 + r), half-chunk seg = tid&1 (k cols seg*32 .. seg*32+31).
    const int br_row = tid >> 1;
    const int br_seg = tid & 1;
    const int o_glob = ntile * 128 + br_row;
    const float* mu_row  = wmu    + (size_t)o_glob * IN_DIM + br_seg * 32;
    const float* sg_row  = g_sigma + (size_t)o_glob * IN_DIM + br_seg * 32;
    const float* eps_row = epsw   + ((size_t)s * OUT_DIM + o_glob) * IN_DIM + br_seg * 32;
    uint32_t b_sts[4];
    #pragma unroll
    for (int jj = 0; jj < 4; ++jj)
        b_sts[jj] = sw128(br_row, br_seg * 4 + jj);

    // A copy slots: 4 quads/thread = full 16KB tile.
    int cp_row[4], cp_kq[4];
    uint32_t cp_dst[4];
    #pragma unroll
    for (int j = 0; j < 4; ++j) {
        const int q = tid + j * 256;
        cp_row[j] = q >> 3;
        cp_kq[j]  = q & 7;
        cp_dst[j] = sw128(cp_row[j], cp_kq[j]);
    }

    // Warp tiling: 2 (M) x 4 (N); warp tile 64 x 32.
    const int wm_idx = wid >> 2;
    const int wn_idx = wid & 3;

    int a_row[4];
    #pragma unroll
    for (int mi = 0; mi < 4; ++mi)
        a_row[mi] = wm_idx * 64 + mi * 16 + (lid & 15);
    const int a_cq0 = (lid >> 4);

    int b_row[2];
    #pragma unroll
    for (int g = 0; g < 2; ++g)
        b_row[g] = wn_idx * 32 + g * 16 + ((lid >> 4) << 3) + (lid & 7);
    const int b_cq0 = ((lid >> 3) & 1);

    float acc[4][4][4];
    #pragma unroll
    for (int mi = 0; mi < 4; ++mi)
        #pragma unroll
        for (int ni = 0; ni < 4; ++ni)
            #pragma unroll
            for (int k = 0; k < 4; ++k)
                acc[mi][ni][k] = 0.0f;

    auto issue_A = [&](int c, int st) {
        const int kb = c * KC;
        const uint32_t sa = smA0 + (uint32_t)st * STAGE_BYTES;
        #pragma unroll
        for (int j = 0; j < 4; ++j) {
            const size_t go = (size_t)cp_row[j] * IN_DIM + kb + cp_kq[j] * 8;
            cp_async16(sa + cp_dst[j], Ag + go);
        }
        asm volatile("cp.async.commit_group;" ::: "memory");
    };

    // Load 32 eps floats (one chunk's worth for this thread) into regs.
    float4 eps_r[8];
    auto load_eps = [&](int c) {
        const float* p = eps_row + c * KC;
        #pragma unroll
        for (int j = 0; j < 8; ++j)
            eps_r[j] = *reinterpret_cast<const float4*>(p + j * 4);
    };

    // Convert held eps regs for chunk c -> half -> STS into stage st.
    auto convert_B = [&](int c, int st) {
        const float* mu_p = mu_row + c * KC;
        const float* sg_p = sg_row + c * KC;
        const uint32_t sb = smB0 + (uint32_t)st * STAGE_BYTES;
        #pragma unroll
        for (int jj = 0; jj < 4; ++jj) {   // each jj: 8 halves = one 16B quad
            const float4 m0 = *reinterpret_cast<const float4*>(mu_p + jj * 8);
            const float4 m1 = *reinterpret_cast<const float4*>(mu_p + jj * 8 + 4);
            const float4 g0 = *reinterpret_cast<const float4*>(sg_p + jj * 8);
            const float4 g1 = *reinterpret_cast<const float4*>(sg_p + jj * 8 + 4);
            const float4 e0 = eps_r[jj * 2];
            const float4 e1 = eps_r[jj * 2 + 1];
            float w0 = fmaf(g0.x, e0.x, m0.x);
            float w1 = fmaf(g0.y, e0.y, m0.y);
            float w2 = fmaf(g0.z, e0.z, m0.z);
            float w3 = fmaf(g0.w, e0.w, m0.w);
            float w4 = fmaf(g1.x, e1.x, m1.x);
            float w5 = fmaf(g1.y, e1.y, m1.y);
            float w6 = fmaf(g1.z, e1.z, m1.z);
            float w7 = fmaf(g1.w, e1.w, m1.w);
            __half2 h0 = __floats2half2_rn(w0, w1);
            __half2 h1 = __floats2half2_rn(w2, w3);
            __half2 h2 = __floats2half2_rn(w4, w5);
            __half2 h3 = __floats2half2_rn(w6, w7);
            asm volatile("st.shared.v4.b32 [%0], {%1, %2, %3, %4};"
                         :: "r"(sb + b_sts[jj]),
                            "r"(*reinterpret_cast<unsigned*>(&h0)),
                            "r"(*reinterpret_cast<unsigned*>(&h1)),
                            "r"(*reinterpret_cast<unsigned*>(&h2)),
                            "r"(*reinterpret_cast<unsigned*>(&h3))
                         : "memory");
        }
    };

    // ---- Prologue ----
    load_eps(0);
    convert_B(0, 0);          // B(0) -> stage0
    issue_A(0, 0);            // A(0) -> stage0
    issue_A(1, 1);            // A(1) -> stage1
    load_eps(1);              // eps(1) held in regs

    for (int c = 0; c < NCHUNK; ++c) {
        const int st = c & 1;

        if (c == NCHUNK - 1) {
            asm volatile("cp.async.wait_group 0;" ::: "memory");
        } else {
            asm volatile("cp.async.wait_group 1;" ::: "memory");
        }
        __syncthreads();   // A(c) + B(c) visible; stage st^1 readers (iter c-1) done

        // Produce B(c+1) into stage st^1 from held eps regs.
        if (c + 1 < NCHUNK) convert_B(c + 1, st ^ 1);
        // Prefetch eps for chunk c+2 (DRAM latency overlaps MMA below).
        if (c + 2 < NCHUNK) load_eps(c + 2);

        const uint32_t sa = smA0 + (uint32_t)st * STAGE_BYTES;
        const uint32_t sb = smB0 + (uint32_t)st * STAGE_BYTES;

        #pragma unroll
        for (int ks = 0; ks < 4; ++ks) {
            uint32_t ar[4][4];
            uint32_t br[2][4];
            #pragma unroll
            for (int mi = 0; mi < 4; ++mi)
                ldmatrix_x4(ar[mi], sa + sw128(a_row[mi], a_cq0 + 2 * ks));
            #pragma unroll
            for (int g = 0; g < 2; ++g)
                ldmatrix_x4(br[g], sb + sw128(b_row[g], b_cq0 + 2 * ks));

            #pragma unroll
            for (int mi = 0; mi < 4; ++mi) {
                #pragma unroll
                for (int ni = 0; ni < 4; ++ni) {
                    const int g = ni >> 1;
                    const int h = (ni & 1) << 1;
                    mma16816(acc[mi][ni], ar[mi], br[g][h + 0], br[g][h + 1]);
                }
            }
        }

        __syncthreads();   // stage st reads done; STS B(c+1) visible next iter
        if (c + 2 < NCHUNK) issue_A(c + 2, st);
    }

    // Epilogue: add bias, store fp32.
    const int row_in = (lid >> 2);
    const int col_in = (lid & 3) * 2;
    #pragma unroll
    for (int mi = 0; mi < 4; ++mi) {
        const int m0 = mtile * 128 + wm_idx * 64 + mi * 16 + row_in;
        float* orow0 = out + ((size_t)(s * B_DIM + m0)     * OUT_DIM) + ntile * 128;
        float* orow1 = out + ((size_t)(s * B_DIM + m0 + 8) * OUT_DIM) + ntile * 128;
        #pragma unroll
        for (int ni = 0; ni < 4; ++ni) {
            const int lcol = wn_idx * 32 + ni * 8 + col_in;
            const float b0 = s_bias[lcol];
            const float b1 = s_bias[lcol + 1];
            float2 v0, v1;
            v0.x = acc[mi][ni][0] + b0;
            v0.y = acc[mi][ni][1] + b1;
            v1.x = acc[mi][ni][2] + b0;
            v1.y = acc[mi][ni][3] + b1;
            *reinterpret_cast<float2*>(orow0 + lcol) = v0;
            *reinterpret_cast<float2*>(orow1 + lcol) = v1;
        }
    }
}

// ---------------------------------------------------------------------------
// Launch
// ---------------------------------------------------------------------------
extern "C" void kernel_launch(void* const* d_in, const int* in_sizes, int n_in,
                              void* d_out, int out_size)
{
    (void)in_sizes; (void)n_in; (void)out_size;
    const float* input  = (const float*)d_in[0];
    const float* wmu    = (const float*)d_in[1];
    const float* wrho   = (const float*)d_in[2];
    const float* bmu    = (const float*)d_in[3];
    const float* brho   = (const float*)d_in[4];
    const float* epsw   = (const float*)d_in[5];
    const float* epsb   = (const float*)d_in[6];
    float* out = (float*)d_out;

    cudaFuncSetAttribute(gemm_fused_kernel,
                         cudaFuncAttributeMaxDynamicSharedMemorySize,
                         GEMM_DYN_SMEM);

    prep_sigma_kernel<<<1024, 256>>>(wrho);
    prep_x_kernel<<<8192, 256>>>(input);
    gemm_fused_kernel<<<dim3(8, 2, 32), 256, GEMM_DYN_SMEM>>>(
        wmu, epsw, bmu, brho, epsb, out);
}

// round 8
// speedup vs baseline: 1.3897x; 1.3897x over previous
#include <cuda_runtime.h>
#include <cuda_fp16.h>
#include <cstdint>

// Problem dims
#define S_DIM   32
#define B_DIM   256
#define IN_DIM  1024
#define OUT_DIM 1024

// ---------------------------------------------------------------------------
// Scratch (device globals)
// ---------------------------------------------------------------------------
__device__ __align__(128) __half g_xf16[(size_t)S_DIM * B_DIM * IN_DIM];   // 17 MB
__device__ __align__(128) __half g_sigh[(size_t)OUT_DIM * IN_DIM];         // 2 MB

__device__ __forceinline__ float softplusf(float x) {
    return (x > 15.0f) ? x : log1pf(expf(x));
}

__device__ __forceinline__ uint32_t smem_to_u32(const void* smem_ptr) {
    uint32_t addr;
    asm("{ .reg .u64 tmp; cvta.to.shared.u64 tmp, %1; cvt.u32.u64 %0, tmp; }"
        : "=r"(addr) : "l"(smem_ptr));
    return addr;
}

__device__ __forceinline__ void cp_async16(uint32_t smem_dst, const void* gptr) {
    asm volatile("cp.async.cg.shared.global [%0], [%1], 16;"
                 :: "r"(smem_dst), "l"(gptr) : "memory");
}

__device__ __forceinline__ void ldmatrix_x4(uint32_t r[4], uint32_t addr) {
    asm volatile("ldmatrix.sync.aligned.m8n8.x4.shared.b16 {%0,%1,%2,%3}, [%4];"
                 : "=r"(r[0]), "=r"(r[1]), "=r"(r[2]), "=r"(r[3]) : "r"(addr));
}

__device__ __forceinline__ void mma16816(float c[4],
                                         const uint32_t a[4],
                                         uint32_t b0, uint32_t b1) {
    asm volatile(
        "mma.sync.aligned.m16n8k16.row.col.f32.f16.f16.f32 "
        "{%0,%1,%2,%3}, {%4,%5,%6,%7}, {%8,%9}, {%0,%1,%2,%3};"
        : "+f"(c[0]), "+f"(c[1]), "+f"(c[2]), "+f"(c[3])
        : "r"(a[0]), "r"(a[1]), "r"(a[2]), "r"(a[3]), "r"(b0), "r"(b1));
}

// SW128 swizzle within a 128-row x 128B tile.
__device__ __forceinline__ uint32_t sw128(int row, int colq) {
    return ((uint32_t)row << 7) + ((uint32_t)((colq ^ (row & 7)) & 7) << 4);
}

// ---------------------------------------------------------------------------
// Kernel 1 (merged prep): blocks [0,8192): x fp32->fp16.
//                         blocks [8192,9216): sigma_h = (half)softplus(rho).
// ---------------------------------------------------------------------------
__global__ __launch_bounds__(256)
void prep_kernel(const float* __restrict__ input,
                 const float* __restrict__ wrho)
{
    if (blockIdx.x < 8192) {
        const int e4 = blockIdx.x * 256 + threadIdx.x;
        const float4 x = *reinterpret_cast<const float4*>(input + (size_t)e4 * 4);
        __half2 h0 = __floats2half2_rn(x.x, x.y);
        __half2 h1 = __floats2half2_rn(x.z, x.w);
        uint2 o;
        o.x = *reinterpret_cast<unsigned*>(&h0);
        o.y = *reinterpret_cast<unsigned*>(&h1);
        reinterpret_cast<uint2*>(g_xf16)[e4] = o;
    } else {
        const int q = (blockIdx.x - 8192) * 256 + threadIdx.x;  // 0..262143
        const float4 r = *reinterpret_cast<const float4*>(wrho + (size_t)q * 4);
        __half2 h0 = __floats2half2_rn(softplusf(r.x), softplusf(r.y));
        __half2 h1 = __floats2half2_rn(softplusf(r.z), softplusf(r.w));
        uint2 o;
        o.x = *reinterpret_cast<unsigned*>(&h0);
        o.y = *reinterpret_cast<unsigned*>(&h1);
        reinterpret_cast<uint2*>(g_sigh)[q] = o;
    }
}

// ---------------------------------------------------------------------------
// Kernel 2: FUSED variational GEMM (mma.sync fp16 in / fp32 acc).
// B tile generated in-SMEM per K-chunk: w = fmaf((f32)sigma_h, eps, mu).
// eps fp32 staged via cp.async into padded SMEM buffer E.
// A via cp.async from g_xf16 (2-stage). B double-buffered (STS).
// CTA M=128 x N=128, K=1024 in 16 chunks of 64. 8 warps (2x4).
// 2 CTAs/SM target: <=128 regs, ~101KB smem.
// ---------------------------------------------------------------------------
#define KC 64
#define NCHUNK 16
#define TILE_BYTES 16384               // A or B stage: 128 rows x 128B
#define EOFF      65536                // after A0,A1,B0,B1
#define EROWSTR   288                  // 72 floats (64 data + 8 pad)
#define ESEGOFF   144
#define EBYTES    (128 * EROWSTR)      // 36864
#define GEMM_DYN_SMEM (1024 + EOFF + EBYTES)   // 103424

__global__ __launch_bounds__(256, 2)
void gemm_fused_kernel(const float* __restrict__ wmu,
                       const float* __restrict__ epsw,
                       const float* __restrict__ bias_mu,
                       const float* __restrict__ bias_rho,
                       const float* __restrict__ eps_b,
                       float* __restrict__ out)
{
    extern __shared__ char dynsmem[];
    __shared__ float s_bias[128];

    const int tid = threadIdx.x;
    const int wid = tid >> 5;
    const int lid = tid & 31;
    const int ntile = blockIdx.x;   // 0..7
    const int mtile = blockIdx.y;   // 0..1
    const int s     = blockIdx.z;   // 0..31

    const uint32_t raw = smem_to_u32(dynsmem);
    const uint32_t base = (raw + 1023u) & ~1023u;
    const uint32_t smA0 = base;                  // A stage st: smA0 + st*16384
    const uint32_t smB0 = base + 2 * TILE_BYTES; // B stage st: smB0 + st*16384
    const uint32_t smE  = base + EOFF;
    char* const smem_c = dynsmem + (base - raw); // generic ptr to 'base'

    // Fused bias
    if (tid < 128) {
        const int o = ntile * 128 + tid;
        s_bias[tid] = fmaf(softplusf(bias_rho[o]), eps_b[s * OUT_DIM + o], bias_mu[o]);
    }

    const __half* Ag  = g_xf16 + (size_t)(s * B_DIM + mtile * 128) * IN_DIM;
    const float* epsC = epsw + ((size_t)s * OUT_DIM + ntile * 128) * IN_DIM;

    // ---- A copy mapping: j=0..3, row = tid>>3 + 32j, kq = tid&7 ----
    const int a_kq = tid & 7;
    const int a_r0 = tid >> 3;
    const uint32_t a_dst0 = sw128(a_r0, a_kq);                     // +4096*j
    const __half* a_src0 = Ag + (size_t)a_r0 * IN_DIM + a_kq * 8;  // +32768*j, +64*c

    // ---- eps copy mapping: j=0..7, row = tid>>4 + 16j, qc = tid&15 ----
    const uint32_t e_dst0 = smE + (uint32_t)(tid >> 4) * EROWSTR
                          + (uint32_t)((tid >> 3) & 1) * ESEGOFF
                          + (uint32_t)(tid & 7) * 16;              // +16*288*j
    const float* e_src0 = epsC + (size_t)(tid >> 4) * IN_DIM + (tid & 15) * 4;

    // ---- convert mapping: row = tid>>1, seg = tid&1 (32 weights/chunk) ----
    const int cv_row = tid >> 1;
    const int cv_seg = tid & 1;
    const int o_glob = ntile * 128 + cv_row;
    const float*  mu0 = wmu    + (size_t)o_glob * IN_DIM + cv_seg * 32;
    const __half* sg0 = g_sigh + (size_t)o_glob * IN_DIM + cv_seg * 32;
    const uint32_t cv_eoff = (uint32_t)cv_row * EROWSTR
                           + (uint32_t)cv_seg * ESEGOFF + EOFF;  // byte off from base
    uint32_t cv_sts[4];
    #pragma unroll
    for (int jj = 0; jj < 4; ++jj)
        cv_sts[jj] = sw128(cv_row, cv_seg * 4 + jj);

    // ---- MMA fragment addressing ----
    const int wm_idx = wid >> 2;
    const int wn_idx = wid & 3;
    int a_row[4];
    #pragma unroll
    for (int mi = 0; mi < 4; ++mi)
        a_row[mi] = wm_idx * 64 + mi * 16 + (lid & 15);
    const int a_cq0 = (lid >> 4);
    int b_row[2];
    #pragma unroll
    for (int g = 0; g < 2; ++g)
        b_row[g] = wn_idx * 32 + g * 16 + ((lid >> 4) << 3) + (lid & 7);
    const int b_cq0 = ((lid >> 3) & 1);

    float acc[4][4][4];
    #pragma unroll
    for (int mi = 0; mi < 4; ++mi)
        #pragma unroll
        for (int ni = 0; ni < 4; ++ni)
            #pragma unroll
            for (int k = 0; k < 4; ++k)
                acc[mi][ni][k] = 0.0f;

    // Issue group {A(c)->stage st, eps(c)->E}
    auto issue_group = [&](int c, int st) {
        const uint32_t sa = smA0 + (uint32_t)st * TILE_BYTES;
        #pragma unroll
        for (int j = 0; j < 4; ++j)
            cp_async16(sa + a_dst0 + j * 4096, a_src0 + (size_t)j * 32768 + c * KC);
        #pragma unroll
        for (int j = 0; j < 8; ++j)
            cp_async16(e_dst0 + j * (16 * EROWSTR), e_src0 + (size_t)j * 16384 + c * KC);
        asm volatile("cp.async.commit_group;" ::: "memory");
    };

    // Convert chunk c from E into B stage stb (two halves to cap live regs).
    auto convert_B = [&](int c, int stb) {
        const float*  mu_p = mu0 + c * KC;
        const __half* sg_p = sg0 + c * KC;
        const uint32_t sb  = smB0 + (uint32_t)stb * TILE_BYTES;
        #pragma unroll
        for (int jh = 0; jh < 2; ++jh) {     // 16 weights per half-pass
            const char* ebase = smem_c + cv_eoff + jh * 64;
            const float4 e0 = *reinterpret_cast<const float4*>(ebase + 0);
            const float4 e1 = *reinterpret_cast<const float4*>(ebase + 16);
            const float4 e2 = *reinterpret_cast<const float4*>(ebase + 32);
            const float4 e3 = *reinterpret_cast<const float4*>(ebase + 48);
            const float4 m0 = *reinterpret_cast<const float4*>(mu_p + jh * 16 + 0);
            const float4 m1 = *reinterpret_cast<const float4*>(mu_p + jh * 16 + 4);
            const float4 m2 = *reinterpret_cast<const float4*>(mu_p + jh * 16 + 8);
            const float4 m3 = *reinterpret_cast<const float4*>(mu_p + jh * 16 + 12);
            // FULL 16 sigma halves = 32 bytes = TWO uint4 loads (R7 bug: had one)
            const uint4 sga = *reinterpret_cast<const uint4*>(sg_p + jh * 16);
            const uint4 sgb = *reinterpret_cast<const uint4*>(sg_p + jh * 16 + 8);
            __half2 sh[8];
            *reinterpret_cast<uint4*>(&sh[0]) = sga;
            *reinterpret_cast<uint4*>(&sh[4]) = sgb;

            const float4 evv[4] = {e0, e1, e2, e3};
            const float4 mvv[4] = {m0, m1, m2, m3};
            float w[16];
            #pragma unroll
            for (int j = 0; j < 4; ++j) {
                const float2 sA = __half22float2(sh[j * 2 + 0]);
                const float2 sB = __half22float2(sh[j * 2 + 1]);
                w[j*4+0] = fmaf(sA.x, evv[j].x, mvv[j].x);
                w[j*4+1] = fmaf(sA.y, evv[j].y, mvv[j].y);
                w[j*4+2] = fmaf(sB.x, evv[j].z, mvv[j].z);
                w[j*4+3] = fmaf(sB.y, evv[j].w, mvv[j].w);
            }
            #pragma unroll
            for (int p = 0; p < 2; ++p) {    // one STS.128 per 8 weights
                __half2 h0 = __floats2half2_rn(w[p*8+0], w[p*8+1]);
                __half2 h1 = __floats2half2_rn(w[p*8+2], w[p*8+3]);
                __half2 h2 = __floats2half2_rn(w[p*8+4], w[p*8+5]);
                __half2 h3 = __floats2half2_rn(w[p*8+6], w[p*8+7]);
                asm volatile("st.shared.v4.b32 [%0], {%1, %2, %3, %4};"
                             :: "r"(sb + cv_sts[jh * 2 + p]),
                                "r"(*reinterpret_cast<unsigned*>(&h0)),
                                "r"(*reinterpret_cast<unsigned*>(&h1)),
                                "r"(*reinterpret_cast<unsigned*>(&h2)),
                                "r"(*reinterpret_cast<unsigned*>(&h3))
                             : "memory");
            }
        }
    };

    // ---- Prologue ----
    issue_group(0, 0);
    asm volatile("cp.async.wait_group 0;" ::: "memory");
    __syncthreads();
    convert_B(0, 0);
    __syncthreads();
    issue_group(1, 1);

    for (int c = 0; c < NCHUNK; ++c) {
        const int st = c & 1;
        const uint32_t sa = smA0 + (uint32_t)st * TILE_BYTES;
        const uint32_t sb = smB0 + (uint32_t)st * TILE_BYTES;

        #pragma unroll
        for (int ks = 0; ks < 4; ++ks) {
            uint32_t ar[4][4];
            uint32_t br[2][4];
            #pragma unroll
            for (int mi = 0; mi < 4; ++mi)
                ldmatrix_x4(ar[mi], sa + sw128(a_row[mi], a_cq0 + 2 * ks));
            #pragma unroll
            for (int g = 0; g < 2; ++g)
                ldmatrix_x4(br[g], sb + sw128(b_row[g], b_cq0 + 2 * ks));
            #pragma unroll
            for (int mi = 0; mi < 4; ++mi) {
                #pragma unroll
                for (int ni = 0; ni < 4; ++ni) {
                    const int g = ni >> 1;
                    const int h = (ni & 1) << 1;
                    mma16816(acc[mi][ni], ar[mi], br[g][h + 0], br[g][h + 1]);
                }
            }
        }

        asm volatile("cp.async.wait_group 0;" ::: "memory");  // A(c+1), eps(c+1) in
        __syncthreads();           // MMA(c) done everywhere; eps visible

        if (c + 1 < NCHUNK) convert_B(c + 1, st ^ 1);
        __syncthreads();           // B(c+1) visible; E reads done

        if (c + 2 < NCHUNK) issue_group(c + 2, st);
    }

    // Epilogue: add bias, store fp32.
    const int row_in = (lid >> 2);
    const int col_in = (lid & 3) * 2;
    #pragma unroll
    for (int mi = 0; mi < 4; ++mi) {
        const int m0 = mtile * 128 + wm_idx * 64 + mi * 16 + row_in;
        float* orow0 = out + ((size_t)(s * B_DIM + m0)     * OUT_DIM) + ntile * 128;
        float* orow1 = out + ((size_t)(s * B_DIM + m0 + 8) * OUT_DIM) + ntile * 128;
        #pragma unroll
        for (int ni = 0; ni < 4; ++ni) {
            const int lcol = wn_idx * 32 + ni * 8 + col_in;
            const float b0 = s_bias[lcol];
            const float b1 = s_bias[lcol + 1];
            float2 v0, v1;
            v0.x = acc[mi][ni][0] + b0;
            v0.y = acc[mi][ni][1] + b1;
            v1.x = acc[mi][ni][2] + b0;
            v1.y = acc[mi][ni][3] + b1;
            *reinterpret_cast<float2*>(orow0 + lcol) = v0;
            *reinterpret_cast<float2*>(orow1 + lcol) = v1;
        }
    }
}

// ---------------------------------------------------------------------------
// Launch
// ---------------------------------------------------------------------------
extern "C" void kernel_launch(void* const* d_in, const int* in_sizes, int n_in,
                              void* d_out, int out_size)
{
    (void)in_sizes; (void)n_in; (void)out_size;
    const float* input  = (const float*)d_in[0];
    const float* wmu    = (const float*)d_in[1];
    const float* wrho   = (const float*)d_in[2];
    const float* bmu    = (const float*)d_in[3];
    const float* brho   = (const float*)d_in[4];
    const float* epsw   = (const float*)d_in[5];
    const float* epsb   = (const float*)d_in[6];
    float* out = (float*)d_out;

    cudaFuncSetAttribute(gemm_fused_kernel,
                         cudaFuncAttributeMaxDynamicSharedMemorySize,
                         GEMM_DYN_SMEM);

    // 8192 x-blocks + 1024 sigma-blocks
    prep_kernel<<<9216, 256>>>(input, wrho);
    // (ntile=8, mtile=2, s=32) = 512 CTAs
    gemm_fused_kernel<<<dim3(8, 2, 32), 256, GEMM_DYN_SMEM>>>(
        wmu, epsw, bmu, brho, epsb, out);
}

// round 9
// speedup vs baseline: 2.6378x; 1.8981x over previous
#include <cuda_runtime.h>
#include <cuda_fp16.h>
#include <cstdint>

// Problem dims
#define S_DIM   32
#define B_DIM   256
#define IN_DIM  1024
#define OUT_DIM 1024

// ---------------------------------------------------------------------------
// Scratch (device globals; the only sanctioned scratch)
// ---------------------------------------------------------------------------
__device__ __align__(128) __half g_wf16[(size_t)S_DIM * OUT_DIM * IN_DIM];  // 67 MB
__device__ __align__(128) __half g_xf16[(size_t)S_DIM * B_DIM * IN_DIM];    // 17 MB

__device__ __forceinline__ float softplusf(float x) {
    return (x > 15.0f) ? x : log1pf(expf(x));
}

__device__ __forceinline__ uint32_t smem_to_u32(const void* smem_ptr) {
    uint32_t addr;
    asm("{ .reg .u64 tmp; cvta.to.shared.u64 tmp, %1; cvt.u32.u64 %0, tmp; }"
        : "=r"(addr) : "l"(smem_ptr));
    return addr;
}

__device__ __forceinline__ void cp_async16(uint32_t smem_dst, const void* gptr) {
    asm volatile("cp.async.cg.shared.global [%0], [%1], 16;"
                 :: "r"(smem_dst), "l"(gptr) : "memory");
}

__device__ __forceinline__ void ldmatrix_x4(uint32_t r[4], uint32_t addr) {
    asm volatile("ldmatrix.sync.aligned.m8n8.x4.shared.b16 {%0,%1,%2,%3}, [%4];"
                 : "=r"(r[0]), "=r"(r[1]), "=r"(r[2]), "=r"(r[3]) : "r"(addr));
}

__device__ __forceinline__ void mma16816(float c[4],
                                         const uint32_t a[4],
                                         uint32_t b0, uint32_t b1) {
    asm volatile(
        "mma.sync.aligned.m16n8k16.row.col.f32.f16.f16.f32 "
        "{%0,%1,%2,%3}, {%4,%5,%6,%7}, {%8,%9}, {%0,%1,%2,%3};"
        : "+f"(c[0]), "+f"(c[1]), "+f"(c[2]), "+f"(c[3])
        : "r"(a[0]), "r"(a[1]), "r"(a[2]), "r"(a[3]), "r"(b0), "r"(b1));
}

// SW128 swizzle: byte address of 16B-quad (row, colq) in a 128-row x 128B tile.
__device__ __forceinline__ uint32_t sw128(int row, int colq) {
    return ((uint32_t)row << 7) + ((uint32_t)((colq ^ (row & 7)) & 7) << 4);
}

// ---------------------------------------------------------------------------
// Kernel 1 (merged prep):
//   blocks [0,1024):    w_f16[s,o,i] = half(mu + softplus(rho)*eps_w)
//                       (one thread per (o,i)-quad, loops 32 samples)
//   blocks [1024,9216): x_f16 = half(input)
// ---------------------------------------------------------------------------
__global__ __launch_bounds__(256)
void prep_all_kernel(const float* __restrict__ input,
                     const float* __restrict__ wmu,
                     const float* __restrict__ wrho,
                     const float* __restrict__ epsw)
{
    if (blockIdx.x < 1024) {
        const int q  = blockIdx.x * 256 + threadIdx.x;   // 0..262143 quads
        const int mi = q * 4;

        const float4 m = *reinterpret_cast<const float4*>(wmu + mi);
        const float4 r = *reinterpret_cast<const float4*>(wrho + mi);
        float4 sg;
        sg.x = softplusf(r.x);
        sg.y = softplusf(r.y);
        sg.z = softplusf(r.z);
        sg.w = softplusf(r.w);

        const size_t plane = (size_t)OUT_DIM * IN_DIM;
        #pragma unroll 4
        for (int s = 0; s < S_DIM; ++s) {
            const float4 ew = *reinterpret_cast<const float4*>(epsw + s * plane + mi);
            float w0 = fmaf(sg.x, ew.x, m.x);
            float w1 = fmaf(sg.y, ew.y, m.y);
            float w2 = fmaf(sg.z, ew.z, m.z);
            float w3 = fmaf(sg.w, ew.w, m.w);
            __half2 h0 = __floats2half2_rn(w0, w1);
            __half2 h1 = __floats2half2_rn(w2, w3);
            uint2 o;
            o.x = *reinterpret_cast<unsigned*>(&h0);
            o.y = *reinterpret_cast<unsigned*>(&h1);
            *reinterpret_cast<uint2*>(g_wf16 + s * plane + mi) = o;
        }
    } else {
        const int e4 = (blockIdx.x - 1024) * 256 + threadIdx.x;  // 0..2097151
        const float4 x = *reinterpret_cast<const float4*>(input + (size_t)e4 * 4);
        __half2 h0 = __floats2half2_rn(x.x, x.y);
        __half2 h1 = __floats2half2_rn(x.z, x.w);
        uint2 o;
        o.x = *reinterpret_cast<unsigned*>(&h0);
        o.y = *reinterpret_cast<unsigned*>(&h1);
        reinterpret_cast<uint2*>(g_xf16)[e4] = o;
    }
}

// ---------------------------------------------------------------------------
// Kernel 2: per-sample GEMM via mma.sync (fp16 in / fp32 accum).
// CTA tile M=128 (batch) x N=128 (out), K=1024 in 16 chunks of 64.
// 8 warps (2x4): warp tile 64x32 -> 4x4 mma.m16n8k16 per k16 step.
// THREE-stage cp.async pipeline, ONE __syncthreads per chunk; copy issue
// precedes the MMA block so LDGSTS overlaps tensor work.
// Grid: (ntile=8, mtile=2, s=32) = 512 CTAs, 256 threads, 2 CTAs/SM.
// ---------------------------------------------------------------------------
#define KC 64
#define NCHUNK (IN_DIM / KC)          // 16
#define TILE_BYTES (128 * 128)        // 16 KB = 1024 16B-quads per tile
#define STAGE_BYTES (2 * TILE_BYTES)  // A + B per stage
#define NSTAGE 3
#define GEMM_DYN_SMEM (1024 + NSTAGE * STAGE_BYTES)   // ~99 KB

__global__ __launch_bounds__(256, 2)
void gemm_f16_kernel(const float* __restrict__ bias_mu,
                     const float* __restrict__ bias_rho,
                     const float* __restrict__ eps_b,
                     float* __restrict__ out)
{
    extern __shared__ char dynsmem[];
    __shared__ float s_bias[128];

    const int tid = threadIdx.x;
    const int wid = tid >> 5;
    const int lid = tid & 31;
    const int ntile = blockIdx.x;   // 0..7
    const int mtile = blockIdx.y;   // 0..1
    const int s     = blockIdx.z;   // 0..31

    uint32_t base = smem_to_u32(dynsmem);
    base = (base + 1023u) & ~1023u;
    const uint32_t smA0 = base;                 // stage st: +st*STAGE_BYTES
    const uint32_t smB0 = base + TILE_BYTES;

    // Fused bias: bias(s,o) = bias_mu[o] + softplus(bias_rho[o]) * eps_b[s,o]
    if (tid < 128) {
        const int o = ntile * 128 + tid;
        s_bias[tid] = fmaf(softplusf(bias_rho[o]), eps_b[s * OUT_DIM + o], bias_mu[o]);
    }

    const __half* Ag = g_xf16 + (size_t)(s * B_DIM + mtile * 128) * IN_DIM;
    const __half* Bg = g_wf16 + (size_t)(s * OUT_DIM + ntile * 128) * IN_DIM;

    // Copy slots: 4 quads per tile per thread (256*4 = 1024 = full 16KB tile).
    int cp_row[4], cp_kq[4];
    uint32_t cp_dst[4];
    #pragma unroll
    for (int j = 0; j < 4; ++j) {
        const int q = tid + j * 256;
        cp_row[j] = q >> 3;
        cp_kq[j]  = q & 7;
        cp_dst[j] = sw128(cp_row[j], cp_kq[j]);
    }

    // Warp tiling: 2 (M) x 4 (N) warps; warp tile 64 x 32.
    const int wm_idx = wid >> 2;
    const int wn_idx = wid & 3;

    int a_row[4];
    #pragma unroll
    for (int mi = 0; mi < 4; ++mi)
        a_row[mi] = wm_idx * 64 + mi * 16 + (lid & 15);
    const int a_cq0 = (lid >> 4);

    int b_row[2];
    #pragma unroll
    for (int g = 0; g < 2; ++g)
        b_row[g] = wn_idx * 32 + g * 16 + ((lid >> 4) << 3) + (lid & 7);
    const int b_cq0 = ((lid >> 3) & 1);

    float acc[4][4][4];
    #pragma unroll
    for (int mi = 0; mi < 4; ++mi)
        #pragma unroll
        for (int ni = 0; ni < 4; ++ni)
            #pragma unroll
            for (int k = 0; k < 4; ++k)
                acc[mi][ni][k] = 0.0f;

    auto issue_chunk = [&](int c, int st) {
        const int kb = c * KC;
        const uint32_t sa = smA0 + (uint32_t)st * STAGE_BYTES;
        const uint32_t sb = smB0 + (uint32_t)st * STAGE_BYTES;
        #pragma unroll
        for (int j = 0; j < 4; ++j) {
            const size_t go = (size_t)cp_row[j] * IN_DIM + kb + cp_kq[j] * 8;
            cp_async16(sa + cp_dst[j], Ag + go);
            cp_async16(sb + cp_dst[j], Bg + go);
        }
        asm volatile("cp.async.commit_group;" ::: "memory");
    };

    // Prologue: stages 0,1 in flight.
    issue_chunk(0, 0);
    issue_chunk(1, 1);

    int st = 0;                       // stage of chunk c (c % 3)
    for (int c = 0; c < NCHUNK; ++c) {
        if (c == NCHUNK - 1) {
            asm volatile("cp.async.wait_group 0;" ::: "memory");
        } else {
            asm volatile("cp.async.wait_group 1;" ::: "memory");
        }
        // One barrier per chunk: makes chunk c's data visible to all warps
        // AND guarantees every warp finished reading stage (c-1)%3 (its MMA
        // precedes this barrier in program order) before we overwrite it.
        __syncthreads();

        // Issue chunk c+2 into stage (c+2)%3 == (c-1)%3 (freed by the barrier).
        if (c + 2 < NCHUNK) {
            int st2 = st + 2; if (st2 >= NSTAGE) st2 -= NSTAGE;
            issue_chunk(c + 2, st2);
        }

        const uint32_t sa = smA0 + (uint32_t)st * STAGE_BYTES;
        const uint32_t sb = smB0 + (uint32_t)st * STAGE_BYTES;

        #pragma unroll
        for (int ks = 0; ks < 4; ++ks) {
            uint32_t ar[4][4];
            uint32_t br[2][4];
            #pragma unroll
            for (int mi = 0; mi < 4; ++mi)
                ldmatrix_x4(ar[mi], sa + sw128(a_row[mi], a_cq0 + 2 * ks));
            #pragma unroll
            for (int g = 0; g < 2; ++g)
                ldmatrix_x4(br[g], sb + sw128(b_row[g], b_cq0 + 2 * ks));

            #pragma unroll
            for (int mi = 0; mi < 4; ++mi) {
                #pragma unroll
                for (int ni = 0; ni < 4; ++ni) {
                    const int g = ni >> 1;
                    const int h = (ni & 1) << 1;
                    mma16816(acc[mi][ni], ar[mi], br[g][h + 0], br[g][h + 1]);
                }
            }
        }

        if (++st >= NSTAGE) st -= NSTAGE;
    }

    // Epilogue: D fragment d0,d1 = [r][c,c+1], d2,d3 = [r+8][c,c+1];
    // r = lid>>2, c = (lid&3)*2 within each 16x8 tile. Add bias, store fp32.
    const int row_in = (lid >> 2);
    const int col_in = (lid & 3) * 2;
    #pragma unroll
    for (int mi = 0; mi < 4; ++mi) {
        const int m0 = mtile * 128 + wm_idx * 64 + mi * 16 + row_in;
        float* orow0 = out + ((size_t)(s * B_DIM + m0)     * OUT_DIM) + ntile * 128;
        float* orow1 = out + ((size_t)(s * B_DIM + m0 + 8) * OUT_DIM) + ntile * 128;
        #pragma unroll
        for (int ni = 0; ni < 4; ++ni) {
            const int lcol = wn_idx * 32 + ni * 8 + col_in;
            const float b0 = s_bias[lcol];
            const float b1 = s_bias[lcol + 1];
            float2 v0, v1;
            v0.x = acc[mi][ni][0] + b0;
            v0.y = acc[mi][ni][1] + b1;
            v1.x = acc[mi][ni][2] + b0;
            v1.y = acc[mi][ni][3] + b1;
            *reinterpret_cast<float2*>(orow0 + lcol) = v0;
            *reinterpret_cast<float2*>(orow1 + lcol) = v1;
        }
    }
}

// ---------------------------------------------------------------------------
// Launch
// ---------------------------------------------------------------------------
extern "C" void kernel_launch(void* const* d_in, const int* in_sizes, int n_in,
                              void* d_out, int out_size)
{
    (void)in_sizes; (void)n_in; (void)out_size;
    const float* input  = (const float*)d_in[0];
    const float* wmu    = (const float*)d_in[1];
    const float* wrho   = (const float*)d_in[2];
    const float* bmu    = (const float*)d_in[3];
    const float* brho   = (const float*)d_in[4];
    const float* epsw   = (const float*)d_in[5];
    const float* epsb   = (const float*)d_in[6];
    float* out = (float*)d_out;

    cudaFuncSetAttribute(gemm_f16_kernel,
                         cudaFuncAttributeMaxDynamicSharedMemorySize,
                         GEMM_DYN_SMEM);

    // 1024 w-blocks + 8192 x-blocks
    prep_all_kernel<<<9216, 256>>>(input, wmu, wrho, epsw);
    // (ntile=8, mtile=2, s=32) = 512 CTAs
    gemm_f16_kernel<<<dim3(8, 2, 32), 256, GEMM_DYN_SMEM>>>(bmu, brho, epsb, out);
}